// round 11
// baseline (speedup 1.0000x reference)
#include <cuda_runtime.h>
#include <cstdint>

#define NTOK   4096
#define DMODEL 1024
#define NEXP   8
#define TOPK   2
#define HEXP   704
#define HSH    1408
#define BK     16

// ---------------- scratch (device globals; no allocation allowed) ----------
__device__ int   g_cnt[NEXP];
__device__ int   g_off[NEXP + 1];
__device__ int   g_topi[NTOK * TOPK];
__device__ float g_topw[NTOK * TOPK];
__device__ int   g_tok[NTOK * TOPK];
__device__ float g_gate[NTOK * TOPK];
__device__ float g_hid_r[NTOK * TOPK * HEXP];   // routed SwiGLU hidden
__device__ float g_hid_s[NTOK * HSH];           // shared-expert hidden

// ---------------- setup kernels ---------------------------------------------
__global__ void zero_kernel() {
    int t = threadIdx.x;
    if (t < NEXP) g_cnt[t] = 0;
}

__global__ void router_kernel(const float* __restrict__ x,
                              const float* __restrict__ Wg) {
    int gw   = (blockIdx.x * blockDim.x + threadIdx.x) >> 5;
    int lane = threadIdx.x & 31;
    if (gw >= NTOK) return;
    const float* xr = x + (size_t)gw * DMODEL;

    float acc[NEXP];
#pragma unroll
    for (int e = 0; e < NEXP; e++) acc[e] = 0.f;
    for (int k = lane; k < DMODEL; k += 32) {
        float xv = xr[k];
#pragma unroll
        for (int e = 0; e < NEXP; e++) acc[e] += xv * Wg[e * DMODEL + k];
    }
#pragma unroll
    for (int e = 0; e < NEXP; e++) {
#pragma unroll
        for (int o = 16; o > 0; o >>= 1)
            acc[e] += __shfl_xor_sync(0xffffffffu, acc[e], o);
    }
    if (lane == 0) {
        float m = acc[0];
#pragma unroll
        for (int e = 1; e < NEXP; e++) m = fmaxf(m, acc[e]);
        float p[NEXP], s = 0.f;
#pragma unroll
        for (int e = 0; e < NEXP; e++) { p[e] = expf(acc[e] - m); s += p[e]; }
        float inv = 1.f / s;
#pragma unroll
        for (int e = 0; e < NEXP; e++) p[e] *= inv;

        int i0 = 0; float v0 = p[0];
#pragma unroll
        for (int e = 1; e < NEXP; e++) if (p[e] > v0) { v0 = p[e]; i0 = e; }
        int i1 = (i0 == 0) ? 1 : 0; float v1 = p[i1];
#pragma unroll
        for (int e = 0; e < NEXP; e++)
            if (e != i0 && p[e] > v1) { v1 = p[e]; i1 = e; }

        float sw = v0 + v1 + 1e-20f;
        g_topi[gw * 2] = i0;  g_topi[gw * 2 + 1] = i1;
        g_topw[gw * 2] = v0 / sw;  g_topw[gw * 2 + 1] = v1 / sw;
        atomicAdd(&g_cnt[i0], 1);
        atomicAdd(&g_cnt[i1], 1);
    }
}

// single block: exclusive scan of g_cnt, then scatter fill (scan+fill fused)
__global__ void scanfill_kernel() {
    __shared__ int s_off[NEXP + 1];
    __shared__ int s_cur[NEXP];
    int tid = threadIdx.x;
    if (tid == 0) {
        int acc = 0;
        s_off[0] = 0;
        for (int e = 0; e < NEXP; e++) {
            acc += g_cnt[e];
            s_off[e + 1] = acc;
            s_cur[e] = 0;
        }
        for (int e = 0; e <= NEXP; e++) g_off[e] = s_off[e];
    }
    __syncthreads();
    for (int n = tid; n < NTOK; n += blockDim.x) {
#pragma unroll
        for (int s = 0; s < TOPK; s++) {
            int e   = g_topi[n * 2 + s];
            int pos = atomicAdd(&s_cur[e], 1);
            int idx = s_off[e] + pos;
            g_tok[idx]  = n;
            g_gate[idx] = g_topw[n * 2 + s];
        }
    }
}

__device__ __forceinline__ float silu_f(float z) {
    return z / (1.f + __expf(-z));
}

// ============ GEMM1 fused: hid = silu(A@W1)*(A@W3) ==========================
// grid (11, 64, 10): z<8 routed expert z; z=8,9 shared-expert column halves.
// CTA 64x64, thread tile 4x4 per matrix, double-buffered smem (1 sync/tile).
__global__ __launch_bounds__(256)
void gemm1_all(const float* __restrict__ x,
               const float* __restrict__ W1,
               const float* __restrict__ W3,
               const float* __restrict__ Ws1,
               const float* __restrict__ Ws3) {
    int z = blockIdx.z;
    bool routed = (z < NEXP);
    int base = 0, ne = NTOK, H, n0;
    const float *B1, *B3;
    float* hid;
    if (routed) {
        base = g_off[z]; ne = g_off[z + 1] - base;
        H = HEXP; hid = g_hid_r;
        n0 = blockIdx.x * 64;
        B1 = W1 + (size_t)z * DMODEL * HEXP + n0;
        B3 = W3 + (size_t)z * DMODEL * HEXP + n0;
    } else {
        H = HSH; hid = g_hid_s;
        n0 = (blockIdx.x + (z - NEXP) * 11) * 64;
        B1 = Ws1 + n0;
        B3 = Ws3 + n0;
    }
    int m0 = blockIdx.y * 64;
    if (m0 >= ne) return;

    __shared__ float As[2][BK][68];
    __shared__ float Bs1[2][BK][64];
    __shared__ float Bs3[2][BK][64];
    __shared__ int   stok[64];

    int tid = threadIdx.x;
    if (tid < 64)
        stok[tid] = routed ? ((m0 + tid < ne) ? g_tok[base + m0 + tid] : -1)
                           : (m0 + tid);
    __syncthreads();

    int ar = tid >> 2, ac = (tid & 3) * 4;
    int tk = stok[ar];
    bool aok = (tk >= 0);
    const float* Arow = x + (size_t)(aok ? tk : 0) * DMODEL;
    int br = tid >> 4, bc = (tid & 15) * 4;

    float4 av  = aok ? *(const float4*)(Arow + ac) : make_float4(0, 0, 0, 0);
    float4 b1v = *(const float4*)(B1 + (size_t)br * H + bc);
    float4 b3v = *(const float4*)(B3 + (size_t)br * H + bc);

    As[0][ac + 0][ar] = av.x; As[0][ac + 1][ar] = av.y;
    As[0][ac + 2][ar] = av.z; As[0][ac + 3][ar] = av.w;
    *(float4*)&Bs1[0][br][bc] = b1v;
    *(float4*)&Bs3[0][br][bc] = b3v;
    __syncthreads();

    int tm0 = (tid >> 4) * 4, tn0 = (tid & 15) * 4;
    float acc1[4][4] = {}, acc3[4][4] = {};

    const int NT = DMODEL / BK;
    for (int t = 0; t < NT; t++) {
        int buf = t & 1;
        int kn  = (t + 1) * BK;
        if (kn < DMODEL) {
            if (aok) av = *(const float4*)(Arow + kn + ac);
            b1v = *(const float4*)(B1 + (size_t)(kn + br) * H + bc);
            b3v = *(const float4*)(B3 + (size_t)(kn + br) * H + bc);
        }
#pragma unroll
        for (int k = 0; k < BK; k++) {
            float4 a  = *(const float4*)&As[buf][k][tm0];
            float4 b1 = *(const float4*)&Bs1[buf][k][tn0];
            float4 b3 = *(const float4*)&Bs3[buf][k][tn0];
            float aa[4]  = { a.x, a.y, a.z, a.w };
            float bb1[4] = { b1.x, b1.y, b1.z, b1.w };
            float bb3[4] = { b3.x, b3.y, b3.z, b3.w };
#pragma unroll
            for (int i = 0; i < 4; i++)
#pragma unroll
                for (int j = 0; j < 4; j++) {
                    acc1[i][j] = fmaf(aa[i], bb1[j], acc1[i][j]);
                    acc3[i][j] = fmaf(aa[i], bb3[j], acc3[i][j]);
                }
        }
        if (kn < DMODEL) {
            int nb = buf ^ 1;
            As[nb][ac + 0][ar] = av.x; As[nb][ac + 1][ar] = av.y;
            As[nb][ac + 2][ar] = av.z; As[nb][ac + 3][ar] = av.w;
            *(float4*)&Bs1[nb][br][bc] = b1v;
            *(float4*)&Bs3[nb][br][bc] = b3v;
        }
        __syncthreads();
    }

#pragma unroll
    for (int i = 0; i < 4; i++) {
        int r = tm0 + i;
        if (m0 + r < ne) {
            float4 hv;
            hv.x = silu_f(acc1[i][0]) * acc3[i][0];
            hv.y = silu_f(acc1[i][1]) * acc3[i][1];
            hv.z = silu_f(acc1[i][2]) * acc3[i][2];
            hv.w = silu_f(acc1[i][3]) * acc3[i][3];
            *(float4*)&hid[(size_t)(base + m0 + r) * H + n0 + tn0] = hv;
        }
    }
}

// ============ GEMM2 fused: out += w * (hid @ W2) ============================
// grid (16, 64, 9): z<8 routed expert z (gate weight); z=8 shared (w=1).
// out pre-zeroed; all paths use atomicAdd so no cross-z ordering needed.
__global__ __launch_bounds__(256)
void gemm2_all(const float* __restrict__ W2,
               const float* __restrict__ Ws2,
               float* __restrict__ out) {
    int z = blockIdx.z;
    bool routed = (z < NEXP);
    int base = 0, ne = NTOK, K;
    const float* Bp;
    const float* hidg;
    int n0 = blockIdx.x * 64;
    if (routed) {
        base = g_off[z]; ne = g_off[z + 1] - base;
        K = HEXP; hidg = g_hid_r;
        Bp = W2 + (size_t)z * HEXP * DMODEL + n0;
    } else {
        K = HSH; hidg = g_hid_s;
        Bp = Ws2 + n0;
    }
    int m0 = blockIdx.y * 64;
    if (m0 >= ne) return;

    __shared__ float As[2][BK][68];
    __shared__ float Bs[2][BK][64];
    __shared__ int   stok[64];
    __shared__ float sgate[64];

    int tid = threadIdx.x;
    if (tid < 64) {
        if (routed) {
            bool v = (m0 + tid < ne);
            stok[tid]  = v ? g_tok[base + m0 + tid] : 0;
            sgate[tid] = v ? g_gate[base + m0 + tid] : 0.f;
        } else {
            stok[tid]  = m0 + tid;
            sgate[tid] = 1.f;
        }
    }
    __syncthreads();

    int ar = tid >> 2, ac = (tid & 3) * 4;
    bool aok = (m0 + ar < ne);
    const float* Arow = hidg + (size_t)(base + m0 + (aok ? ar : 0)) * K;
    int br = tid >> 4, bc = (tid & 15) * 4;

    float4 av = aok ? *(const float4*)(Arow + ac) : make_float4(0, 0, 0, 0);
    float4 bv = *(const float4*)(Bp + (size_t)br * DMODEL + bc);

    As[0][ac + 0][ar] = av.x; As[0][ac + 1][ar] = av.y;
    As[0][ac + 2][ar] = av.z; As[0][ac + 3][ar] = av.w;
    *(float4*)&Bs[0][br][bc] = bv;
    __syncthreads();

    int tm0 = (tid >> 4) * 4, tn0 = (tid & 15) * 4;
    float acc[4][4] = {};

    const int NT_ = K / BK;
    for (int t = 0; t < NT_; t++) {
        int buf = t & 1;
        int kn  = (t + 1) * BK;
        if (kn < K) {
            if (aok) av = *(const float4*)(Arow + kn + ac);
            bv = *(const float4*)(Bp + (size_t)(kn + br) * DMODEL + bc);
        }
#pragma unroll
        for (int k = 0; k < BK; k++) {
            float4 a = *(const float4*)&As[buf][k][tm0];
            float4 b = *(const float4*)&Bs[buf][k][tn0];
            float aa[4] = { a.x, a.y, a.z, a.w };
            float bb[4] = { b.x, b.y, b.z, b.w };
#pragma unroll
            for (int i = 0; i < 4; i++)
#pragma unroll
                for (int j = 0; j < 4; j++)
                    acc[i][j] = fmaf(aa[i], bb[j], acc[i][j]);
        }
        if (kn < K) {
            int nb = buf ^ 1;
            As[nb][ac + 0][ar] = av.x; As[nb][ac + 1][ar] = av.y;
            As[nb][ac + 2][ar] = av.z; As[nb][ac + 3][ar] = av.w;
            *(float4*)&Bs[nb][br][bc] = bv;
        }
        __syncthreads();
    }

#pragma unroll
    for (int i = 0; i < 4; i++) {
        int r = tm0 + i;
        if (m0 + r < ne) {
            int   tk = stok[r];
            float w  = sgate[r];
            float* op = out + (size_t)tk * DMODEL + n0 + tn0;
            atomicAdd(op + 0, w * acc[i][0]);
            atomicAdd(op + 1, w * acc[i][1]);
            atomicAdd(op + 2, w * acc[i][2]);
            atomicAdd(op + 3, w * acc[i][3]);
        }
    }
}

// ---------------- launch -----------------------------------------------------
extern "C" void kernel_launch(void* const* d_in, const int* in_sizes, int n_in,
                              void* d_out, int out_size) {
    const float* x   = (const float*)d_in[0];
    const float* Wg  = (const float*)d_in[1];
    const float* W1  = (const float*)d_in[2];
    const float* W3  = (const float*)d_in[3];
    const float* W2  = (const float*)d_in[4];
    const float* Ws1 = (const float*)d_in[5];
    const float* Ws3 = (const float*)d_in[6];
    const float* Ws2 = (const float*)d_in[7];
    float* out = (float*)d_out;

    zero_kernel<<<1, 32>>>();
    router_kernel<<<NTOK / 8, 256>>>(x, Wg);
    scanfill_kernel<<<1, 1024>>>();
    cudaMemsetAsync(out, 0, (size_t)NTOK * DMODEL * sizeof(float));

    // fused up-proj: routed (z=0..7) + shared halves (z=8,9)
    gemm1_all<<<dim3(HEXP / 64, NTOK / 64, 10), 256>>>(x, W1, W3, Ws1, Ws3);
    // fused down-proj: routed (z=0..7) + shared (z=8), all atomic into out
    gemm2_all<<<dim3(DMODEL / 64, NTOK / 64, 9), 256>>>(W2, Ws2, out);
}

// round 12
// speedup vs baseline: 1.0428x; 1.0428x over previous
#include <cuda_runtime.h>
#include <cstdint>

#define NTOK   4096
#define DMODEL 1024
#define NEXP   8
#define TOPK   2
#define HEXP   704
#define HSH    1408
#define BK     16

// ---------------- scratch (device globals; no allocation allowed) ----------
__device__ int   g_cnt[NEXP];
__device__ int   g_off[NEXP + 1];
__device__ int   g_topi[NTOK * TOPK];
__device__ float g_topw[NTOK * TOPK];
__device__ int   g_tok[NTOK * TOPK];
__device__ float g_gate[NTOK * TOPK];
__device__ float g_hid_r[NTOK * TOPK * HEXP];   // routed SwiGLU hidden
__device__ float g_hid_s[NTOK * HSH];           // shared-expert hidden

// ---------------- setup kernels ---------------------------------------------
__global__ void zero_kernel() {
    int t = threadIdx.x;
    if (t < NEXP) g_cnt[t] = 0;
}

__global__ void router_kernel(const float* __restrict__ x,
                              const float* __restrict__ Wg) {
    int gw   = (blockIdx.x * blockDim.x + threadIdx.x) >> 5;
    int lane = threadIdx.x & 31;
    if (gw >= NTOK) return;
    const float* xr = x + (size_t)gw * DMODEL;

    float acc[NEXP];
#pragma unroll
    for (int e = 0; e < NEXP; e++) acc[e] = 0.f;
    for (int k = lane; k < DMODEL; k += 32) {
        float xv = xr[k];
#pragma unroll
        for (int e = 0; e < NEXP; e++) acc[e] += xv * Wg[e * DMODEL + k];
    }
#pragma unroll
    for (int e = 0; e < NEXP; e++) {
#pragma unroll
        for (int o = 16; o > 0; o >>= 1)
            acc[e] += __shfl_xor_sync(0xffffffffu, acc[e], o);
    }
    if (lane == 0) {
        float m = acc[0];
#pragma unroll
        for (int e = 1; e < NEXP; e++) m = fmaxf(m, acc[e]);
        float p[NEXP], s = 0.f;
#pragma unroll
        for (int e = 0; e < NEXP; e++) { p[e] = expf(acc[e] - m); s += p[e]; }
        float inv = 1.f / s;
#pragma unroll
        for (int e = 0; e < NEXP; e++) p[e] *= inv;

        int i0 = 0; float v0 = p[0];
#pragma unroll
        for (int e = 1; e < NEXP; e++) if (p[e] > v0) { v0 = p[e]; i0 = e; }
        int i1 = (i0 == 0) ? 1 : 0; float v1 = p[i1];
#pragma unroll
        for (int e = 0; e < NEXP; e++)
            if (e != i0 && p[e] > v1) { v1 = p[e]; i1 = e; }

        float sw = v0 + v1 + 1e-20f;
        g_topi[gw * 2] = i0;  g_topi[gw * 2 + 1] = i1;
        g_topw[gw * 2] = v0 / sw;  g_topw[gw * 2 + 1] = v1 / sw;
        atomicAdd(&g_cnt[i0], 1);
        atomicAdd(&g_cnt[i1], 1);
    }
}

// single block: exclusive scan of g_cnt, then scatter fill
__global__ void scanfill_kernel() {
    __shared__ int s_off[NEXP + 1];
    __shared__ int s_cur[NEXP];
    int tid = threadIdx.x;
    if (tid == 0) {
        int acc = 0;
        s_off[0] = 0;
        for (int e = 0; e < NEXP; e++) {
            acc += g_cnt[e];
            s_off[e + 1] = acc;
            s_cur[e] = 0;
        }
        for (int e = 0; e <= NEXP; e++) g_off[e] = s_off[e];
    }
    __syncthreads();
    for (int n = tid; n < NTOK; n += blockDim.x) {
#pragma unroll
        for (int s = 0; s < TOPK; s++) {
            int e   = g_topi[n * 2 + s];
            int pos = atomicAdd(&s_cur[e], 1);
            int idx = s_off[e] + pos;
            g_tok[idx]  = n;
            g_gate[idx] = g_topw[n * 2 + s];
        }
    }
}

__device__ __forceinline__ float silu_f(float z) {
    return z / (1.f + __expf(-z));
}

// ============ GEMM1 fused: hid = silu(A@W1)*(A@W3) ==========================
// grid (11, 32, 10). CTA 128x64, thread tile 4 rows x (8+8) cols (split-col),
// 256 thr = 32(ty) x 8(tx). Double-buffered smem, 1 sync/tile.
__global__ __launch_bounds__(256, 2)
void gemm1_all(const float* __restrict__ x,
               const float* __restrict__ W1,
               const float* __restrict__ W3,
               const float* __restrict__ Ws1,
               const float* __restrict__ Ws3) {
    int z = blockIdx.z;
    bool routed = (z < NEXP);
    int base = 0, ne = NTOK, H, n0;
    const float *B1, *B3;
    float* hid;
    if (routed) {
        base = g_off[z]; ne = g_off[z + 1] - base;
        H = HEXP; hid = g_hid_r;
        n0 = blockIdx.x * 64;
        B1 = W1 + (size_t)z * DMODEL * HEXP + n0;
        B3 = W3 + (size_t)z * DMODEL * HEXP + n0;
    } else {
        H = HSH; hid = g_hid_s;
        n0 = (blockIdx.x + (z - NEXP) * 11) * 64;
        B1 = Ws1 + n0;
        B3 = Ws3 + n0;
    }
    int m0 = blockIdx.y * 128;
    if (m0 >= ne) return;

    __shared__ float As[2][BK][132];
    __shared__ float Bs1[2][BK][64];
    __shared__ float Bs3[2][BK][64];
    __shared__ int   stok[128];

    int tid = threadIdx.x;
    if (tid < 128)
        stok[tid] = routed ? ((m0 + tid < ne) ? g_tok[base + m0 + tid] : -1)
                           : (m0 + tid);
    __syncthreads();

    // A loader: row = tid>>1, k-octet = (tid&1)*8 (2 float4)
    int ar = tid >> 1, ac = (tid & 1) * 8;
    int tk = stok[ar];
    bool aok = (tk >= 0);
    const float* Arow = x + (size_t)(aok ? tk : 0) * DMODEL;
    // B loader: k = tid>>4, n-quad = (tid&15)*4 (1 float4 per matrix)
    int br = tid >> 4, bc = (tid & 15) * 4;

    float4 av0 = make_float4(0, 0, 0, 0), av1 = make_float4(0, 0, 0, 0);
    if (aok) {
        av0 = *(const float4*)(Arow + ac);
        av1 = *(const float4*)(Arow + ac + 4);
    }
    float4 b1v = *(const float4*)(B1 + (size_t)br * H + bc);
    float4 b3v = *(const float4*)(B3 + (size_t)br * H + bc);

    As[0][ac + 0][ar] = av0.x; As[0][ac + 1][ar] = av0.y;
    As[0][ac + 2][ar] = av0.z; As[0][ac + 3][ar] = av0.w;
    As[0][ac + 4][ar] = av1.x; As[0][ac + 5][ar] = av1.y;
    As[0][ac + 6][ar] = av1.z; As[0][ac + 7][ar] = av1.w;
    *(float4*)&Bs1[0][br][bc] = b1v;
    *(float4*)&Bs3[0][br][bc] = b3v;
    __syncthreads();

    int ty = tid >> 3, tx = tid & 7;
    int trow = ty * 4, tc = tx * 4;
    float acc1[4][8] = {}, acc3[4][8] = {};

    const int NT = DMODEL / BK;
    for (int t = 0; t < NT; t++) {
        int buf = t & 1;
        int kn  = (t + 1) * BK;
        if (kn < DMODEL) {
            if (aok) {
                av0 = *(const float4*)(Arow + kn + ac);
                av1 = *(const float4*)(Arow + kn + ac + 4);
            }
            b1v = *(const float4*)(B1 + (size_t)(kn + br) * H + bc);
            b3v = *(const float4*)(B3 + (size_t)(kn + br) * H + bc);
        }
#pragma unroll
        for (int k = 0; k < BK; k++) {
            float4 a  = *(const float4*)&As[buf][k][trow];
            float4 p0 = *(const float4*)&Bs1[buf][k][tc];
            float4 p1 = *(const float4*)&Bs1[buf][k][tc + 32];
            float4 q0 = *(const float4*)&Bs3[buf][k][tc];
            float4 q1 = *(const float4*)&Bs3[buf][k][tc + 32];
            float aa[4] = { a.x, a.y, a.z, a.w };
            float pp[8] = { p0.x, p0.y, p0.z, p0.w, p1.x, p1.y, p1.z, p1.w };
            float qq[8] = { q0.x, q0.y, q0.z, q0.w, q1.x, q1.y, q1.z, q1.w };
#pragma unroll
            for (int i = 0; i < 4; i++)
#pragma unroll
                for (int j = 0; j < 8; j++) {
                    acc1[i][j] = fmaf(aa[i], pp[j], acc1[i][j]);
                    acc3[i][j] = fmaf(aa[i], qq[j], acc3[i][j]);
                }
        }
        if (kn < DMODEL) {
            int nb = buf ^ 1;
            As[nb][ac + 0][ar] = av0.x; As[nb][ac + 1][ar] = av0.y;
            As[nb][ac + 2][ar] = av0.z; As[nb][ac + 3][ar] = av0.w;
            As[nb][ac + 4][ar] = av1.x; As[nb][ac + 5][ar] = av1.y;
            As[nb][ac + 6][ar] = av1.z; As[nb][ac + 7][ar] = av1.w;
            *(float4*)&Bs1[nb][br][bc] = b1v;
            *(float4*)&Bs3[nb][br][bc] = b3v;
        }
        __syncthreads();
    }

#pragma unroll
    for (int i = 0; i < 4; i++) {
        int r = trow + i;
        if (m0 + r < ne) {
            size_t rowoff = (size_t)(base + m0 + r) * H + n0;
            float4 h0, h1;
            h0.x = silu_f(acc1[i][0]) * acc3[i][0];
            h0.y = silu_f(acc1[i][1]) * acc3[i][1];
            h0.z = silu_f(acc1[i][2]) * acc3[i][2];
            h0.w = silu_f(acc1[i][3]) * acc3[i][3];
            h1.x = silu_f(acc1[i][4]) * acc3[i][4];
            h1.y = silu_f(acc1[i][5]) * acc3[i][5];
            h1.z = silu_f(acc1[i][6]) * acc3[i][6];
            h1.w = silu_f(acc1[i][7]) * acc3[i][7];
            *(float4*)&hid[rowoff + tc]      = h0;
            *(float4*)&hid[rowoff + tc + 32] = h1;
        }
    }
}

// ============ GEMM2 fused: out += w * (hid @ W2) ============================
// grid (8, 64, 9). CTA 64x128, thread tile 4x(4+4) split-col,
// 256 thr = 16(ty) x 16(tx). out pre-zeroed, all paths atomicAdd.
__global__ __launch_bounds__(256)
void gemm2_all(const float* __restrict__ W2,
               const float* __restrict__ Ws2,
               float* __restrict__ out) {
    int z = blockIdx.z;
    bool routed = (z < NEXP);
    int base = 0, ne = NTOK, K;
    const float* Bp;
    const float* hidg;
    int n0 = blockIdx.x * 128;
    if (routed) {
        base = g_off[z]; ne = g_off[z + 1] - base;
        K = HEXP; hidg = g_hid_r;
        Bp = W2 + (size_t)z * HEXP * DMODEL + n0;
    } else {
        K = HSH; hidg = g_hid_s;
        Bp = Ws2 + n0;
    }
    int m0 = blockIdx.y * 64;
    if (m0 >= ne) return;

    __shared__ float As[2][BK][68];
    __shared__ float Bs[2][BK][128];
    __shared__ int   stok[64];
    __shared__ float sgate[64];

    int tid = threadIdx.x;
    if (tid < 64) {
        if (routed) {
            bool v = (m0 + tid < ne);
            stok[tid]  = v ? g_tok[base + m0 + tid] : 0;
            sgate[tid] = v ? g_gate[base + m0 + tid] : 0.f;
        } else {
            stok[tid]  = m0 + tid;
            sgate[tid] = 1.f;
        }
    }
    __syncthreads();

    int ar = tid >> 2, ac = (tid & 3) * 4;
    bool aok = (m0 + ar < ne);
    const float* Arow = hidg + (size_t)(base + m0 + (aok ? ar : 0)) * K;
    // B loader: 2 float4 per thread (cols bc and bc+64)
    int br = tid >> 4, bc = (tid & 15) * 4;

    float4 av = aok ? *(const float4*)(Arow + ac) : make_float4(0, 0, 0, 0);
    float4 bv0 = *(const float4*)(Bp + (size_t)br * DMODEL + bc);
    float4 bv1 = *(const float4*)(Bp + (size_t)br * DMODEL + bc + 64);

    As[0][ac + 0][ar] = av.x; As[0][ac + 1][ar] = av.y;
    As[0][ac + 2][ar] = av.z; As[0][ac + 3][ar] = av.w;
    *(float4*)&Bs[0][br][bc]      = bv0;
    *(float4*)&Bs[0][br][bc + 64] = bv1;
    __syncthreads();

    int ty = tid >> 4, tx = tid & 15;
    int trow = ty * 4, tc = tx * 4;
    float acc[4][8] = {};

    const int NT_ = K / BK;
    for (int t = 0; t < NT_; t++) {
        int buf = t & 1;
        int kn  = (t + 1) * BK;
        if (kn < K) {
            if (aok) av = *(const float4*)(Arow + kn + ac);
            bv0 = *(const float4*)(Bp + (size_t)(kn + br) * DMODEL + bc);
            bv1 = *(const float4*)(Bp + (size_t)(kn + br) * DMODEL + bc + 64);
        }
#pragma unroll
        for (int k = 0; k < BK; k++) {
            float4 a  = *(const float4*)&As[buf][k][trow];
            float4 b0 = *(const float4*)&Bs[buf][k][tc];
            float4 b1 = *(const float4*)&Bs[buf][k][tc + 64];
            float aa[4] = { a.x, a.y, a.z, a.w };
            float bb[8] = { b0.x, b0.y, b0.z, b0.w, b1.x, b1.y, b1.z, b1.w };
#pragma unroll
            for (int i = 0; i < 4; i++)
#pragma unroll
                for (int j = 0; j < 8; j++)
                    acc[i][j] = fmaf(aa[i], bb[j], acc[i][j]);
        }
        if (kn < K) {
            int nb = buf ^ 1;
            As[nb][ac + 0][ar] = av.x; As[nb][ac + 1][ar] = av.y;
            As[nb][ac + 2][ar] = av.z; As[nb][ac + 3][ar] = av.w;
            *(float4*)&Bs[nb][br][bc]      = bv0;
            *(float4*)&Bs[nb][br][bc + 64] = bv1;
        }
        __syncthreads();
    }

#pragma unroll
    for (int i = 0; i < 4; i++) {
        int r = trow + i;
        if (m0 + r < ne) {
            int   tk = stok[r];
            float w  = sgate[r];
            float* op = out + (size_t)tk * DMODEL + n0;
#pragma unroll
            for (int j = 0; j < 4; j++) {
                atomicAdd(op + tc + j,      w * acc[i][j]);
                atomicAdd(op + tc + 64 + j, w * acc[i][j + 4]);
            }
        }
    }
}

// ---------------- launch -----------------------------------------------------
extern "C" void kernel_launch(void* const* d_in, const int* in_sizes, int n_in,
                              void* d_out, int out_size) {
    const float* x   = (const float*)d_in[0];
    const float* Wg  = (const float*)d_in[1];
    const float* W1  = (const float*)d_in[2];
    const float* W3  = (const float*)d_in[3];
    const float* W2  = (const float*)d_in[4];
    const float* Ws1 = (const float*)d_in[5];
    const float* Ws3 = (const float*)d_in[6];
    const float* Ws2 = (const float*)d_in[7];
    float* out = (float*)d_out;

    zero_kernel<<<1, 32>>>();
    router_kernel<<<NTOK / 8, 256>>>(x, Wg);
    scanfill_kernel<<<1, 1024>>>();
    cudaMemsetAsync(out, 0, (size_t)NTOK * DMODEL * sizeof(float));

    // fused up-proj: routed (z=0..7) + shared halves (z=8,9)
    gemm1_all<<<dim3(HEXP / 64, NTOK / 128, 10), 256>>>(x, W1, W3, Ws1, Ws3);
    // fused down-proj: routed (z=0..7) + shared (z=8), all atomic into out
    gemm2_all<<<dim3(DMODEL / 128, NTOK / 64, 9), 256>>>(W2, Ws2, out);
}